// round 2
// baseline (speedup 1.0000x reference)
#include <cuda_runtime.h>

#define Dm 1024
#define MAXB 8
#define TW 8            // tokens per warp in k3
#define TB 64           // tokens per block in k3 (8 warps * TW)
#define MAXCH 32        // chunks per b (S=2048 / 64)
#define DCH 32          // d-chunks for partial GEMVs

// ---------------- scratch ---------------------------------------------------
__device__ float g_part[DCH * MAXB * Dm];      // 1 MB
__device__ float g_q0[MAXB * Dm];
__device__ float g_u[MAXB * Dm];
__device__ float g_xw[MAXB * Dm];
__device__ float g_r[MAXB * Dm];
__device__ float g_pm[MAXB * MAXCH];
__device__ float g_ps[MAXB * MAXCH];
__device__ float g_pacc[MAXB * MAXCH * Dm];    // 1 MB

// ---------------- helpers ---------------------------------------------------
__device__ __forceinline__ float blk_reduce(float v, volatile float* sbuf) {
    int lane = threadIdx.x & 31, w = threadIdx.x >> 5;
#pragma unroll
    for (int o = 16; o; o >>= 1) v += __shfl_xor_sync(0xffffffffu, v, o);
    __syncthreads();
    if (lane == 0) sbuf[w] = v;
    __syncthreads();
    int nw = (blockDim.x + 31) >> 5;
    if (w == 0) {
        float r = (lane < nw) ? sbuf[lane] : 0.f;
#pragma unroll
        for (int o = 16; o; o >>= 1) r += __shfl_xor_sync(0xffffffffu, r, o);
        if (lane == 0) sbuf[0] = r;
    }
    __syncthreads();
    return sbuf[0];
}

// ---------------- partial skinny GEMV: part[dc,b,j] += A[b,d0:d0+32]@W -----
// grid (Dm/128, DCH), block 128
__global__ void gemv8_part(const float* __restrict__ A, long astride,
                           const float* __restrict__ W,
                           float* __restrict__ part, int B) {
    __shared__ float as[MAXB][32];
    int j  = blockIdx.x * 128 + threadIdx.x;
    int d0 = blockIdx.y * 32;
    for (int i = threadIdx.x; i < MAXB * 32; i += 128) {
        int b = i >> 5, dd = i & 31;
        as[b][dd] = (b < B) ? A[(long)b * astride + d0 + dd] : 0.f;
    }
    __syncthreads();
    float acc[MAXB];
#pragma unroll
    for (int b = 0; b < MAXB; b++) acc[b] = 0.f;
#pragma unroll 8
    for (int dd = 0; dd < 32; dd++) {
        float w = W[(long)(d0 + dd) * Dm + j];
#pragma unroll
        for (int b = 0; b < MAXB; b++) acc[b] = fmaf(as[b][dd], w, acc[b]);
    }
#pragma unroll
    for (int b = 0; b < MAXB; b++)
        part[((long)blockIdx.y * MAXB + b) * Dm + j] = acc[b];
}

// ---------------- reduce partials + bias ------------------------------------
__global__ void reduce_part(const float* __restrict__ part,
                            const float* __restrict__ bias,
                            float* __restrict__ out) {
    int idx = blockIdx.x * 256 + threadIdx.x;
    int b = idx >> 10, j = idx & (Dm - 1);
    float s = bias[j];
#pragma unroll 8
    for (int dc = 0; dc < DCH; dc++)
        s += part[((long)dc * MAXB + b) * Dm + j];
    out[idx] = s;
}

// ---------------- u[b,d] = Wk[d,:] . q0[b,:]  (warp per row; 4 warps/blk) --
__global__ void k2_u(const float* __restrict__ Wk,
                     const float* __restrict__ q0,
                     float* __restrict__ u) {
    __shared__ float4 q0s[MAXB * 256];               // 32 KB
    for (int i = threadIdx.x; i < MAXB * 256; i += 128)
        q0s[i] = ((const float4*)q0)[i];
    __syncthreads();
    int wid = threadIdx.x >> 5, lane = threadIdx.x & 31;
    int d = blockIdx.x * 4 + wid;
    const float4* wrow = (const float4*)(Wk + (long)d * Dm);
    float acc[MAXB];
#pragma unroll
    for (int b = 0; b < MAXB; b++) acc[b] = 0.f;
#pragma unroll
    for (int i = 0; i < 8; i++) {
        float4 w = wrow[lane + 32 * i];
#pragma unroll
        for (int b = 0; b < MAXB; b++) {
            float4 q = q0s[b * 256 + lane + 32 * i];
            acc[b] += w.x * q.x + w.y * q.y + w.z * q.z + w.w * q.w;
        }
    }
#pragma unroll
    for (int b = 0; b < MAXB; b++)
#pragma unroll
        for (int o = 16; o; o >>= 1)
            acc[b] += __shfl_xor_sync(0xffffffffu, acc[b], o);
    if (lane == 0)
#pragma unroll
        for (int b = 0; b < MAXB; b++) u[(long)b * Dm + d] = acc[b];
}

// ---------------- k3: single-pass online-softmax streaming ------------------
// grid (S/TB, B), block 256 = 8 warps. Each warp: TW tokens, online softmax,
// register-resident accumulator. Block merges 8 warp partials in smem.
__global__ void __launch_bounds__(256, 2) k3_stream(
        const float* __restrict__ x, const float* __restrict__ u,
        float* __restrict__ pm, float* __restrict__ ps,
        float* __restrict__ pacc, int S, int nblk) {
    int b = blockIdx.y, blk = blockIdx.x;
    int wid = threadIdx.x >> 5, lane = threadIdx.x & 31;
    __shared__ float4 us[256];                       // 4 KB
    __shared__ float4 mb[8][256];                    // 32 KB merge buffer
    __shared__ float wm[8], ws[8];

    us[threadIdx.x] = ((const float4*)(u + (long)b * Dm))[threadIdx.x];
    __syncthreads();

    int t0 = blk * TB + wid * TW;
    const float4* xb = (const float4*)(x + ((long)b * S + t0) * Dm);

    float m = -1e30f, s = 0.f;
    float4 acc[8];
#pragma unroll
    for (int i = 0; i < 8; i++) acc[i] = make_float4(0.f, 0.f, 0.f, 0.f);

#pragma unroll 2
    for (int k = 0; k < TW; k++) {
        const float4* xr = xb + (long)k * 256;
        float4 xv[8];
#pragma unroll
        for (int i = 0; i < 8; i++) xv[i] = xr[lane + 32 * i];
        float d = 0.f;
#pragma unroll
        for (int i = 0; i < 8; i++) {
            float4 uv = us[lane + 32 * i];
            d += xv[i].x * uv.x + xv[i].y * uv.y + xv[i].z * uv.z + xv[i].w * uv.w;
        }
#pragma unroll
        for (int o = 16; o; o >>= 1) d += __shfl_xor_sync(0xffffffffu, d, o);
        d *= 0.03125f;                               // 1/sqrt(1024)
        float mn = fmaxf(m, d);
        float c = __expf(m - mn);                    // first iter: exp(-huge)=0
        float p = __expf(d - mn);
        s = s * c + p;
#pragma unroll
        for (int i = 0; i < 8; i++) {
            acc[i].x = acc[i].x * c + p * xv[i].x;
            acc[i].y = acc[i].y * c + p * xv[i].y;
            acc[i].z = acc[i].z * c + p * xv[i].z;
            acc[i].w = acc[i].w * c + p * xv[i].w;
        }
        m = mn;
    }

    // block merge of 8 warp partials
    if (lane == 0) wm[wid] = m;
    __syncthreads();
    float M = wm[0];
#pragma unroll
    for (int w = 1; w < 8; w++) M = fmaxf(M, wm[w]);
    float f = __expf(m - M);
    if (lane == 0) ws[wid] = s * f;
#pragma unroll
    for (int i = 0; i < 8; i++) {
        float4 a = acc[i];
        a.x *= f; a.y *= f; a.z *= f; a.w *= f;
        mb[wid][lane + 32 * i] = a;
    }
    __syncthreads();
    float4 tot = mb[0][threadIdx.x];
#pragma unroll
    for (int w = 1; w < 8; w++) {
        float4 v = mb[w][threadIdx.x];
        tot.x += v.x; tot.y += v.y; tot.z += v.z; tot.w += v.w;
    }
    long ci = (long)b * nblk + blk;
    ((float4*)pacc)[ci * 256 + threadIdx.x] = tot;
    if (threadIdx.x == 0) {
        float sb = 0.f;
#pragma unroll
        for (int w = 0; w < 8; w++) sb += ws[w];
        pm[ci] = M; ps[ci] = sb;
    }
}

// ---------------- merge chunk partials -> xw[b,:] ---------------------------
__global__ void k4a_merge(const float* __restrict__ pm,
                          const float* __restrict__ ps,
                          const float* __restrict__ pacc,
                          float* __restrict__ xw, int nch) {
    int b = blockIdx.x, tid = threadIdx.x;
    __shared__ float f[MAXCH];
    __shared__ float red[2];
    if (tid < nch) f[tid] = pm[b * nch + tid];
    __syncthreads();
    if (tid == 0) {
        float m = -1e30f;
        for (int c = 0; c < nch; c++) m = fmaxf(m, f[c]);
        red[0] = m;
    }
    __syncthreads();
    float mstar = red[0];
    if (tid < nch) f[tid] = __expf(f[tid] - mstar);
    __syncthreads();
    if (tid == 0) {
        float s = 0.f;
        for (int c = 0; c < nch; c++) s += ps[b * nch + c] * f[c];
        red[1] = 1.f / s;
    }
    __syncthreads();
    float sinv = red[1];
    float4 acc = make_float4(0.f, 0.f, 0.f, 0.f);
    const float4* pa = (const float4*)pacc;
#pragma unroll 8
    for (int c = 0; c < nch; c++) {
        float fc = f[c];
        float4 v = pa[((long)b * nch + c) * 256 + tid];
        acc.x = fmaf(fc, v.x, acc.x);
        acc.y = fmaf(fc, v.y, acc.y);
        acc.z = fmaf(fc, v.z, acc.z);
        acc.w = fmaf(fc, v.w, acc.w);
    }
    acc.x *= sinv; acc.y *= sinv; acc.z *= sinv; acc.w *= sinv;
    ((float4*)xw)[b * 256 + tid] = acc;
}

// ---------------- r = LN1( (xw@Wv + bv) + x[b,0,:] ) ------------------------
__global__ void __launch_bounds__(1024) k4c_ln(
        const float* __restrict__ part, const float* __restrict__ bv,
        const float* __restrict__ x, long xstride,
        const float* __restrict__ g1, const float* __restrict__ b1,
        float* __restrict__ r) {
    int b = blockIdx.x, j = threadIdx.x;
    __shared__ float sbuf[32];
    float v = bv[j] + x[(long)b * xstride + j];
#pragma unroll 8
    for (int dc = 0; dc < DCH; dc++)
        v += part[((long)dc * MAXB + b) * Dm + j];
    float sum = blk_reduce(v, sbuf);
    float sq  = blk_reduce(v * v, sbuf);
    float mu  = sum * (1.f / Dm);
    float var = sq * (1.f / Dm) - mu * mu;
    float rstd = rsqrtf(var + 1e-5f);
    r[(long)b * Dm + j] = (v - mu) * rstd * g1[j] + b1[j];
}

// ---------------- h = LN2(relu(r@Wd+bd) + r); logits = h@Wc + bc ------------
__global__ void __launch_bounds__(1024) k4e_final(
        const float* __restrict__ part, const float* __restrict__ bd,
        const float* __restrict__ r,
        const float* __restrict__ g2, const float* __restrict__ b2,
        const float* __restrict__ Wc, const float* __restrict__ bc,
        float* __restrict__ out) {
    int b = blockIdx.x, j = threadIdx.x;
    __shared__ float sbuf[32];
    float v = bd[j];
#pragma unroll 8
    for (int dc = 0; dc < DCH; dc++)
        v += part[((long)dc * MAXB + b) * Dm + j];
    float rv = r[(long)b * Dm + j];
    v = fmaxf(v, 0.f) + rv;
    float sum = blk_reduce(v, sbuf);
    float sq  = blk_reduce(v * v, sbuf);
    float mu  = sum * (1.f / Dm);
    float var = sq * (1.f / Dm) - mu * mu;
    float rstd = rsqrtf(var + 1e-5f);
    float h = (v - mu) * rstd * g2[j] + b2[j];
    float l0 = blk_reduce(h * Wc[j * 2 + 0], sbuf);
    float l1 = blk_reduce(h * Wc[j * 2 + 1], sbuf);
    if (j == 0) {
        out[b * 2 + 0] = l0 + bc[0];
        out[b * 2 + 1] = l1 + bc[1];
    }
}

// ---------------- host -------------------------------------------------------
extern "C" void kernel_launch(void* const* d_in, const int* in_sizes, int n_in,
                              void* d_out, int out_size) {
    const float* x  = (const float*)d_in[0];
    const float* Wq = (const float*)d_in[1];
    const float* bq = (const float*)d_in[2];
    const float* Wk = (const float*)d_in[3];
    // d_in[4] = bk: constant over t in scores -> cancels in softmax; unused.
    const float* Wv = (const float*)d_in[5];
    const float* bv = (const float*)d_in[6];
    const float* Wd = (const float*)d_in[7];
    const float* bd = (const float*)d_in[8];
    const float* g1 = (const float*)d_in[9];
    const float* b1 = (const float*)d_in[10];
    const float* g2 = (const float*)d_in[11];
    const float* b2 = (const float*)d_in[12];
    const float* Wc = (const float*)d_in[13];
    const float* bc = (const float*)d_in[14];
    float* out = (float*)d_out;

    int  B   = out_size / 2;                       // 8
    long xsz = (long)in_sizes[0];
    int  S   = (int)(xsz / ((long)B * Dm));        // 2048
    int  nblk = S / TB;                            // 32

    float *part, *q0, *u, *xw, *r, *pm, *ps, *pacc;
    cudaGetSymbolAddress((void**)&part, g_part);
    cudaGetSymbolAddress((void**)&q0,   g_q0);
    cudaGetSymbolAddress((void**)&u,    g_u);
    cudaGetSymbolAddress((void**)&xw,   g_xw);
    cudaGetSymbolAddress((void**)&r,    g_r);
    cudaGetSymbolAddress((void**)&pm,   g_pm);
    cudaGetSymbolAddress((void**)&ps,   g_ps);
    cudaGetSymbolAddress((void**)&pacc, g_pacc);

    dim3 gp(Dm / 128, DCH);                        // 256 blocks / GEMV

    // q0 = x[:,0,:] @ Wq + bq
    gemv8_part<<<gp, 128>>>(x, (long)S * Dm, Wq, part, B);
    reduce_part<<<(B * Dm) / 256, 256>>>(part, bq, q0);

    // u[b] = Wk @ q0[b]
    k2_u<<<Dm / 4, 128>>>(Wk, q0, u);

    // single-pass online-softmax streaming over x
    dim3 g3(nblk, B);
    k3_stream<<<g3, 256>>>(x, u, pm, ps, pacc, S, nblk);

    // merge -> xw[b] = sum_t attn_t x[b,t]
    k4a_merge<<<B, 256>>>(pm, ps, pacc, xw, nblk);

    // r = LN1(xw@Wv + bv + x0)
    gemv8_part<<<gp, 128>>>(xw, (long)Dm, Wv, part, B);
    k4c_ln<<<B, 1024>>>(part, bv, x, (long)S * Dm, g1, b1, r);

    // h = LN2(relu(r@Wd + bd) + r); logits = h@Wc + bc
    gemv8_part<<<gp, 128>>>(r, (long)Dm, Wd, part, B);
    k4e_final<<<B, 1024>>>(part, bd, r, g2, b2, Wc, bc, out);
}

// round 3
// speedup vs baseline: 1.2076x; 1.2076x over previous
#include <cuda_runtime.h>

#define Dm 1024
#define MAXB 8
#define TC 16           // tokens per chunk in k3 (S=2048 -> 128 chunks)
#define MAXCH 128
#define DCH 32          // d-chunks for partial GEMVs

// ---------------- scratch ---------------------------------------------------
__device__ float g_part[DCH * MAXB * Dm];      // 1 MB
__device__ float g_q0[MAXB * Dm];
__device__ float g_u[MAXB * Dm];
__device__ float g_xw[MAXB * Dm];
__device__ float g_r[MAXB * Dm];
__device__ float g_pm[MAXB * MAXCH];
__device__ float g_ps[MAXB * MAXCH];
__device__ float g_pacc[MAXB * MAXCH * Dm];    // 4 MB

// ---------------- helpers ---------------------------------------------------
__device__ __forceinline__ float blk_reduce(float v, volatile float* sbuf) {
    int lane = threadIdx.x & 31, w = threadIdx.x >> 5;
#pragma unroll
    for (int o = 16; o; o >>= 1) v += __shfl_xor_sync(0xffffffffu, v, o);
    __syncthreads();
    if (lane == 0) sbuf[w] = v;
    __syncthreads();
    int nw = (blockDim.x + 31) >> 5;
    if (w == 0) {
        float r = (lane < nw) ? sbuf[lane] : 0.f;
#pragma unroll
        for (int o = 16; o; o >>= 1) r += __shfl_xor_sync(0xffffffffu, r, o);
        if (lane == 0) sbuf[0] = r;
    }
    __syncthreads();
    return sbuf[0];
}

// ---------------- partial skinny GEMV (R1 config) ---------------------------
// grid (Dm/256, DCH), block 256
__global__ void gemv8_part(const float* __restrict__ A, long astride,
                           const float* __restrict__ W,
                           float* __restrict__ part, int B) {
    __shared__ float as[MAXB][32];
    int j  = blockIdx.x * 256 + threadIdx.x;
    int d0 = blockIdx.y * 32;
    int t  = threadIdx.x;
    {
        int b = t >> 5, dd = t & 31;
        as[b][dd] = (b < B) ? A[(long)b * astride + d0 + dd] : 0.f;
    }
    __syncthreads();
    float acc[MAXB];
#pragma unroll
    for (int b = 0; b < MAXB; b++) acc[b] = 0.f;
#pragma unroll 8
    for (int dd = 0; dd < 32; dd++) {
        float w = W[(long)(d0 + dd) * Dm + j];
#pragma unroll
        for (int b = 0; b < MAXB; b++) acc[b] = fmaf(as[b][dd], w, acc[b]);
    }
#pragma unroll
    for (int b = 0; b < MAXB; b++)
        part[((long)blockIdx.y * MAXB + b) * Dm + j] = acc[b];
}

// ---------------- reduce partials + bias ------------------------------------
__global__ void reduce_part(const float* __restrict__ part,
                            const float* __restrict__ bias,
                            float* __restrict__ out) {
    int idx = blockIdx.x * 256 + threadIdx.x;
    int b = idx >> 10, j = idx & (Dm - 1);
    float s = bias[j];
#pragma unroll 8
    for (int dc = 0; dc < DCH; dc++)
        s += part[((long)dc * MAXB + b) * Dm + j];
    out[idx] = s;
}

// ---------------- u[b,d] = Wk[d,:] . q0[b,:]  (R1 config: 8 rows/block) ----
__global__ void k2_u(const float* __restrict__ Wk,
                     const float* __restrict__ q0,
                     float* __restrict__ u) {
    __shared__ float4 q0s[MAXB * 256];               // 32 KB
    for (int i = threadIdx.x; i < MAXB * 256; i += 256)
        q0s[i] = ((const float4*)q0)[i];
    __syncthreads();
    int wid = threadIdx.x >> 5, lane = threadIdx.x & 31;
    int d = blockIdx.x * 8 + wid;
    const float4* wrow = (const float4*)(Wk + (long)d * Dm);
    float acc[MAXB];
#pragma unroll
    for (int b = 0; b < MAXB; b++) acc[b] = 0.f;
#pragma unroll
    for (int i = 0; i < 8; i++) {
        float4 w = wrow[lane + 32 * i];
#pragma unroll
        for (int b = 0; b < MAXB; b++) {
            float4 q = q0s[b * 256 + lane + 32 * i];
            acc[b] += w.x * q.x + w.y * q.y + w.z * q.z + w.w * q.w;
        }
    }
#pragma unroll
    for (int b = 0; b < MAXB; b++)
#pragma unroll
        for (int o = 16; o; o >>= 1)
            acc[b] += __shfl_xor_sync(0xffffffffu, acc[b], o);
    if (lane == 0)
#pragma unroll
        for (int b = 0; b < MAXB; b++) u[(long)b * Dm + d] = acc[b];
}

// ---------------- k3: two-phase streaming, TC=16, 1024 blocks ---------------
// grid (S/TC, B), block 256 = 8 warps; each warp does 2 tokens in phase A.
__global__ void k3_stream(const float* __restrict__ x,
                          const float* __restrict__ u,
                          float* __restrict__ pm, float* __restrict__ ps,
                          float* __restrict__ pacc, int S, int nch) {
    int b = blockIdx.y, ch = blockIdx.x;
    int t0 = ch * TC;
    __shared__ float4 us[256];
    __shared__ float sc[TC];
    __shared__ float red[2];
    us[threadIdx.x] = ((const float4*)(u + (long)b * Dm))[threadIdx.x];
    __syncthreads();

    int wid = threadIdx.x >> 5, lane = threadIdx.x & 31;
    const float4* xb = (const float4*)(x + (long)b * S * Dm);
#pragma unroll
    for (int k = 0; k < 2; k++) {
        int tl = wid * 2 + k;
        const float4* xr = xb + (long)(t0 + tl) * 256;
        float a = 0.f;
#pragma unroll
        for (int i = 0; i < 8; i++) {
            float4 xv = xr[lane + 32 * i];
            float4 uv = us[lane + 32 * i];
            a += xv.x * uv.x + xv.y * uv.y + xv.z * uv.z + xv.w * uv.w;
        }
#pragma unroll
        for (int o = 16; o; o >>= 1) a += __shfl_xor_sync(0xffffffffu, a, o);
        if (lane == 0) sc[tl] = a * 0.03125f;        // 1/sqrt(1024)
    }
    __syncthreads();

    if (threadIdx.x < 32) {
        float v = (threadIdx.x < TC) ? sc[threadIdx.x] : -1e30f;
        float m = v;
#pragma unroll
        for (int o = 16; o; o >>= 1) m = fmaxf(m, __shfl_xor_sync(0xffffffffu, m, o));
        float p = __expf(v - m);
        float s = p;
#pragma unroll
        for (int o = 16; o; o >>= 1) s += __shfl_xor_sync(0xffffffffu, s, o);
        if (threadIdx.x < TC) sc[threadIdx.x] = p;
        if (threadIdx.x == 0) { red[0] = m; red[1] = s; }
    }
    __syncthreads();

    float4 acc = make_float4(0.f, 0.f, 0.f, 0.f);
    const float4* xr0 = xb + (long)t0 * 256;
#pragma unroll 4
    for (int t = 0; t < TC; t++) {
        float p = sc[t];
        float4 xv = xr0[(long)t * 256 + threadIdx.x];
        acc.x = fmaf(p, xv.x, acc.x);
        acc.y = fmaf(p, xv.y, acc.y);
        acc.z = fmaf(p, xv.z, acc.z);
        acc.w = fmaf(p, xv.w, acc.w);
    }
    long ci = (long)b * nch + ch;
    ((float4*)pacc)[ci * 256 + threadIdx.x] = acc;
    if (threadIdx.x == 0) { pm[ci] = red[0]; ps[ci] = red[1]; }
}

// ---------------- merge chunk partials -> xw[b,:] (parallel over j) --------
// grid (B, 16), block 128: each block covers 16 float4-j's; 8-way chunk split.
__global__ void k4a_merge(const float* __restrict__ pm,
                          const float* __restrict__ ps,
                          const float* __restrict__ pacc,
                          float* __restrict__ xw, int nch) {
    int b = blockIdx.x, jc = blockIdx.y;
    int tid = threadIdx.x;
    __shared__ float f[MAXCH];
    __shared__ float red;
    __shared__ float4 partial[8][16];

    // all threads: load pm, compute max (serial over nch in 1 warp, cheap)
    if (tid < nch) f[tid] = pm[b * nch + tid];
    __syncthreads();
    if (tid < 32) {
        float m = -1e30f;
        for (int c = tid; c < nch; c += 32) m = fmaxf(m, f[c]);
#pragma unroll
        for (int o = 16; o; o >>= 1) m = fmaxf(m, __shfl_xor_sync(0xffffffffu, m, o));
        float s = 0.f;
        for (int c = tid; c < nch; c += 32) {
            float e = __expf(f[c] - m);
            f[c] = e;                                 // safe: each c touched once
            s += e * ps[b * nch + c];
        }
#pragma unroll
        for (int o = 16; o; o >>= 1) s += __shfl_xor_sync(0xffffffffu, s, o);
        if (tid == 0) red = 1.f / s;
    }
    __syncthreads();

    int jj = tid & 15;            // float4 index within this block's 16
    int cp = tid >> 4;            // chunk partition 0..7
    int j4 = jc * 16 + jj;        // global float4 index (0..255)
    const float4* pa = (const float4*)pacc;
    float4 acc = make_float4(0.f, 0.f, 0.f, 0.f);
    for (int c = cp; c < nch; c += 8) {
        float fc = f[c];
        float4 v = pa[((long)b * nch + c) * 256 + j4];
        acc.x = fmaf(fc, v.x, acc.x);
        acc.y = fmaf(fc, v.y, acc.y);
        acc.z = fmaf(fc, v.z, acc.z);
        acc.w = fmaf(fc, v.w, acc.w);
    }
    partial[cp][jj] = acc;
    __syncthreads();
    if (tid < 16) {
        float4 t = partial[0][tid];
#pragma unroll
        for (int p = 1; p < 8; p++) {
            float4 v = partial[p][tid];
            t.x += v.x; t.y += v.y; t.z += v.z; t.w += v.w;
        }
        float sinv = red;
        t.x *= sinv; t.y *= sinv; t.z *= sinv; t.w *= sinv;
        ((float4*)xw)[b * 256 + jc * 16 + tid] = t;
    }
}

// ---------------- r = LN1( (xw@Wv + bv) + x[b,0,:] ) ------------------------
__global__ void __launch_bounds__(1024) k4c_ln(
        const float* __restrict__ part, const float* __restrict__ bv,
        const float* __restrict__ x, long xstride,
        const float* __restrict__ g1, const float* __restrict__ b1,
        float* __restrict__ r) {
    int b = blockIdx.x, j = threadIdx.x;
    __shared__ float sbuf[32];
    float v = bv[j] + x[(long)b * xstride + j];
#pragma unroll 8
    for (int dc = 0; dc < DCH; dc++)
        v += part[((long)dc * MAXB + b) * Dm + j];
    float sum = blk_reduce(v, sbuf);
    float sq  = blk_reduce(v * v, sbuf);
    float mu  = sum * (1.f / Dm);
    float var = sq * (1.f / Dm) - mu * mu;
    float rstd = rsqrtf(var + 1e-5f);
    r[(long)b * Dm + j] = (v - mu) * rstd * g1[j] + b1[j];
}

// ---------------- h = LN2(relu(r@Wd+bd) + r); logits = h@Wc + bc ------------
__global__ void __launch_bounds__(1024) k4e_final(
        const float* __restrict__ part, const float* __restrict__ bd,
        const float* __restrict__ r,
        const float* __restrict__ g2, const float* __restrict__ b2,
        const float* __restrict__ Wc, const float* __restrict__ bc,
        float* __restrict__ out) {
    int b = blockIdx.x, j = threadIdx.x;
    __shared__ float sbuf[32];
    float v = bd[j];
#pragma unroll 8
    for (int dc = 0; dc < DCH; dc++)
        v += part[((long)dc * MAXB + b) * Dm + j];
    float rv = r[(long)b * Dm + j];
    v = fmaxf(v, 0.f) + rv;
    float sum = blk_reduce(v, sbuf);
    float sq  = blk_reduce(v * v, sbuf);
    float mu  = sum * (1.f / Dm);
    float var = sq * (1.f / Dm) - mu * mu;
    float rstd = rsqrtf(var + 1e-5f);
    float h = (v - mu) * rstd * g2[j] + b2[j];
    float l0 = blk_reduce(h * Wc[j * 2 + 0], sbuf);
    float l1 = blk_reduce(h * Wc[j * 2 + 1], sbuf);
    if (j == 0) {
        out[b * 2 + 0] = l0 + bc[0];
        out[b * 2 + 1] = l1 + bc[1];
    }
}

// ---------------- host -------------------------------------------------------
extern "C" void kernel_launch(void* const* d_in, const int* in_sizes, int n_in,
                              void* d_out, int out_size) {
    const float* x  = (const float*)d_in[0];
    const float* Wq = (const float*)d_in[1];
    const float* bq = (const float*)d_in[2];
    const float* Wk = (const float*)d_in[3];
    // d_in[4] = bk: constant over t in scores -> cancels in softmax; unused.
    const float* Wv = (const float*)d_in[5];
    const float* bv = (const float*)d_in[6];
    const float* Wd = (const float*)d_in[7];
    const float* bd = (const float*)d_in[8];
    const float* g1 = (const float*)d_in[9];
    const float* b1 = (const float*)d_in[10];
    const float* g2 = (const float*)d_in[11];
    const float* b2 = (const float*)d_in[12];
    const float* Wc = (const float*)d_in[13];
    const float* bc = (const float*)d_in[14];
    float* out = (float*)d_out;

    int  B   = out_size / 2;                       // 8
    long xsz = (long)in_sizes[0];
    int  S   = (int)(xsz / ((long)B * Dm));        // 2048
    int  nch = S / TC;                             // 128

    float *part, *q0, *u, *xw, *r, *pm, *ps, *pacc;
    cudaGetSymbolAddress((void**)&part, g_part);
    cudaGetSymbolAddress((void**)&q0,   g_q0);
    cudaGetSymbolAddress((void**)&u,    g_u);
    cudaGetSymbolAddress((void**)&xw,   g_xw);
    cudaGetSymbolAddress((void**)&r,    g_r);
    cudaGetSymbolAddress((void**)&pm,   g_pm);
    cudaGetSymbolAddress((void**)&ps,   g_ps);
    cudaGetSymbolAddress((void**)&pacc, g_pacc);

    dim3 gp(Dm / 256, DCH);                        // 128 blocks / GEMV

    // q0 = x[:,0,:] @ Wq + bq
    gemv8_part<<<gp, 256>>>(x, (long)S * Dm, Wq, part, B);
    reduce_part<<<(B * Dm) / 256, 256>>>(part, bq, q0);

    // u[b] = Wk @ q0[b]
    k2_u<<<Dm / 8, 256>>>(Wk, q0, u);

    // streaming: scores + chunk softmax + weighted-x partials
    dim3 g3(nch, B);
    k3_stream<<<g3, 256>>>(x, u, pm, ps, pacc, S, nch);

    // merge -> xw[b] = sum_t attn_t x[b,t]
    dim3 gm(B, 16);
    k4a_merge<<<gm, 128>>>(pm, ps, pacc, xw, nch);

    // r = LN1(xw@Wv + bv + x0)
    gemv8_part<<<gp, 256>>>(xw, (long)Dm, Wv, part, B);
    k4c_ln<<<B, 1024>>>(part, bv, x, (long)S * Dm, g1, b1, r);

    // h = LN2(relu(r@Wd + bd) + r); logits = h@Wc + bc
    gemv8_part<<<gp, 256>>>(r, (long)Dm, Wd, part, B);
    k4e_final<<<B, 1024>>>(part, bd, r, g2, b2, Wc, bc, out);
}